// round 1
// baseline (speedup 1.0000x reference)
#include <cuda_runtime.h>

#define B_ 256
#define N_ 1024
#define D_ 64
#define NPAIR 512               // pairs per batch sequence
#define NTILES 2048             // (B_*NPAIR)/64
#define LDA 65                  // padded stride for transposed X/H tile
#define LDO 132                 // padded stride for output tile

#define PRED_OFF (B_*11*N_)                  // 2883584
#define NORM_OFF (PRED_OFF + B_*N_*11*2)     // 8650752

typedef unsigned long long u64;

// ---------------- persistent device scratch ----------------
__device__ float g_e[2][(size_t)B_ * N_ * D_];   // ping-pong embeddings, 2x64MB
__device__ unsigned char g_v[2][B_ * N_];        // ping-pong bits
__device__ float g_W1[128 * 128];                // fused first-layer weight [k][j]; j<64 cn, j>=64 bn
__device__ float g_W2[2 * 64 * 64];              // [0]=cn_W2, [1]=bn_W2, each [k][j]
__device__ float g_B1[128];                      // cn_b1 | bn_b1
__device__ float g_B2[128];                      // cn_b2 | bn_b2
__device__ float g_T[2 * 64];                    // lab_emb[v] @ bn_W1[128:192,:]

// ---------------- f32x2 helpers ----------------
__device__ __forceinline__ u64 dup2(float v) {
    u64 r; asm("mov.b64 %0, {%1,%1};" : "=l"(r) : "f"(v)); return r;
}
__device__ __forceinline__ void unp2(u64 p, float& lo, float& hi) {
    asm("mov.b64 {%0,%1}, %2;" : "=f"(lo), "=f"(hi) : "l"(p));
}
__device__ __forceinline__ u64 ffma2(u64 a, u64 b, u64 c) {
    u64 d; asm("fma.rn.f32x2 %0, %1, %2, %3;" : "=l"(d) : "l"(a), "l"(b), "l"(c)); return d;
}

// ---------------- weight preprocessing ----------------
__global__ void prep_kernel(const float* cnW1, const float* bnW1,
                            const float* cnW2, const float* bnW2,
                            const float* cnb1, const float* bnb1,
                            const float* cnb2, const float* bnb2,
                            const float* lab) {
    int t = threadIdx.x;
    for (int i = t; i < 128 * 128; i += 256) {
        int k = i >> 7, j = i & 127;
        g_W1[i] = (j < 64) ? cnW1[k * 64 + j] : bnW1[k * 64 + (j - 64)];
    }
    for (int i = t; i < 4096; i += 256) {
        g_W2[i] = cnW2[i];
        g_W2[4096 + i] = bnW2[i];
    }
    if (t < 64) {
        g_B1[t] = cnb1[t]; g_B1[64 + t] = bnb1[t];
        g_B2[t] = cnb2[t]; g_B2[64 + t] = bnb2[t];
    }
    if (t < 128) {
        int v = t >> 6, j = t & 63;
        float s = 0.f;
        for (int m = 0; m < 64; m++) s += lab[v * 64 + m] * bnW1[(128 + m) * 64 + j];
        g_T[t] = s;
    }
}

// ---------------- stage 0: embedding + bit copy ----------------
__global__ void stage0_kernel(const int* __restrict__ x, const float* __restrict__ y,
                              const float* __restrict__ embW, const float* __restrict__ embb) {
    int tid0 = blockIdx.x * blockDim.x + threadIdx.x;
    if (tid0 < B_ * N_) g_v[0][tid0] = (unsigned char)x[tid0];
    for (int f = tid0; f < B_ * N_ * 16; f += gridDim.x * blockDim.x) {
        int pos = f >> 4;
        int c = (f & 15) << 2;
        float y0 = y[pos * 2 + 0], y1 = y[pos * 2 + 1];
        float4 w0 = *(const float4*)(embW + c);
        float4 w1 = *(const float4*)(embW + 64 + c);
        float4 bb = *(const float4*)(embb + c);
        float4 e;
        e.x = fmaf(y0, w0.x, fmaf(y1, w1.x, bb.x));
        e.y = fmaf(y0, w0.y, fmaf(y1, w1.y, bb.y));
        e.z = fmaf(y0, w0.z, fmaf(y1, w1.z, bb.z));
        e.w = fmaf(y0, w0.w, fmaf(y1, w1.w, bb.w));
        *(float4*)(&g_e[0][(size_t)pos * 64 + c]) = e;
    }
}

// ---------------- stage-0 head (softmax / loss / norm), warp per position ----------------
__global__ void head0_kernel(const float* __restrict__ llrW, const float* __restrict__ llrb,
                             float* __restrict__ out) {
    int g = blockIdx.x * blockDim.x + threadIdx.x;
    int wid = g >> 5, lane = g & 31;
    if (wid >= B_ * N_) return;
    const float* e = g_e[0] + (size_t)wid * 64;
    float e0 = e[lane], e1 = e[lane + 32];
    float l0 = e0 * llrW[lane * 2]       + e1 * llrW[(lane + 32) * 2];
    float l1 = e0 * llrW[lane * 2 + 1]   + e1 * llrW[(lane + 32) * 2 + 1];
    float nr = e0 * e0 + e1 * e1;
    for (int o = 16; o; o >>= 1) {
        l0 += __shfl_xor_sync(0xffffffffu, l0, o);
        l1 += __shfl_xor_sync(0xffffffffu, l1, o);
        nr += __shfl_xor_sync(0xffffffffu, nr, o);
    }
    if (lane == 0) {
        l0 += llrb[0]; l1 += llrb[1];
        float m = fmaxf(l0, l1);
        float x0 = expf(l0 - m), x1 = expf(l1 - m);
        float inv = 1.f / (x0 + x1);
        float p0 = x0 * inv, p1 = x1 * inv;
        int v = g_v[0][wid];
        float pt = v ? p1 : p0;
        float loss = -logf(fminf(fmaxf(pt, 1e-7f), 1.f));
        int b = wid >> 10, p = wid & 1023;
        out[(size_t)b * (11 * N_) + p] = loss;                                 // s = 0
        float* pr = out + PRED_OFF + (((size_t)(b * N_ + p)) * 11) * 2;
        pr[0] = p0; pr[1] = p1;
        out[NORM_OFF + (size_t)b * (11 * N_) + p] = sqrtf(nr);
    }
}

// ---------------- main butterfly-stage kernel ----------------
// dyn smem layout (floats)
#define OFF_W1 0
#define OFF_W2 16384
#define OFF_X  24576          // 128 x LDA transposed X tile (reused as H tile)
#define OFF_O  32896          // 64 x LDO output tile
#define OFF_B1 41344
#define OFF_B2 41472
#define OFF_T  41600
#define OFF_LW 41728
#define OFF_LB 41856
#define SMEM_FLOATS 41864
#define SMEM_BYTES (SMEM_FLOATS * 4)

__global__ void __launch_bounds__(256, 1)
stage_kernel(int scope, int src, int s,
             const float* __restrict__ llrW, const float* __restrict__ llrb,
             float* __restrict__ out) {
    extern __shared__ float sm[];
    float* sW1 = sm + OFF_W1;
    float* sW2 = sm + OFF_W2;
    float* sX  = sm + OFF_X;
    float* sO  = sm + OFF_O;
    float* sB1 = sm + OFF_B1;
    float* sB2 = sm + OFF_B2;
    float* sT  = sm + OFF_T;
    float* sLW = sm + OFF_LW;
    float* sLb = sm + OFF_LB;
    __shared__ unsigned char sVx[64], sVe[64];

    int tid = threadIdx.x;
    for (int i = tid; i < 128 * 128; i += 256) sW1[i] = g_W1[i];
    for (int i = tid; i < 8192; i += 256) sW2[i] = g_W2[i];
    if (tid < 128) { sB1[tid] = g_B1[tid]; sB2[tid] = g_B2[tid]; sT[tid] = g_T[tid]; sLW[tid] = llrW[tid]; }
    if (tid < 2) sLb[tid] = llrb[tid];
    __syncthreads();

    const int half = scope >> 1;
    const int dst = src ^ 1;
    const int tx = tid & 15;       // col group: cols jb..jb+7
    const int ty = tid >> 4;       // row group: rows r0..r0+3
    const int r0 = ty * 4;
    const int jb = tx * 8;
    const bool right = (jb >= 64);

    for (int tile = blockIdx.x; tile < NTILES; tile += gridDim.x) {
        int b  = tile >> 3;
        int j0 = (tile & 7) << 6;                // pair base within batch
        const float* eb = g_e[src] + (size_t)b * (N_ * 64);
        const unsigned char* vb = g_v[src] + b * N_;

        // ---- bits for this tile ----
        if (tid < 64) {
            int j = j0 + tid;
            int so = ((j & ~(half - 1)) << 1) | (j & (half - 1));
            unsigned char vo = vb[so], ve = vb[so + half];
            sVx[tid] = (unsigned char)((vo + ve) & 1);
            sVe[tid] = ve;
        }
        // ---- gather X tile (64 pairs x 128 dims), store transposed (k-major) ----
        for (int c = tid; c < 128 * 16; c += 256) {
            int rh = c >> 4;                      // row-half 0..127
            int f  = c & 15;                      // float4 within 64 dims
            int r  = rh >> 1, hs = rh & 1;
            int j  = j0 + r;
            int so = ((j & ~(half - 1)) << 1) | (j & (half - 1));
            int srcpos = so + hs * half;
            float4 val = *(const float4*)(eb + (size_t)srcpos * 64 + f * 4);
            int k = hs * 64 + f * 4;
            sX[(k + 0) * LDA + r] = val.x;
            sX[(k + 1) * LDA + r] = val.y;
            sX[(k + 2) * LDA + r] = val.z;
            sX[(k + 3) * LDA + r] = val.w;
        }
        __syncthreads();

        // ---- GEMM1: [64 x 128] @ [128 x 128] with f32x2 packed FMAs ----
        u64 acc[4][4];
        #pragma unroll
        for (int i = 0; i < 4; i++)
            #pragma unroll
            for (int jj = 0; jj < 4; jj++) acc[i][jj] = 0ull;

        #pragma unroll 4
        for (int k = 0; k < 128; k++) {
            const float* xk = sX + k * LDA + r0;
            u64 a0 = dup2(xk[0]), a1 = dup2(xk[1]), a2 = dup2(xk[2]), a3 = dup2(xk[3]);
            const u64* wr = (const u64*)(sW1 + k * 128 + jb);
            u64 b0 = wr[0], b1 = wr[1], b2 = wr[2], b3 = wr[3];
            acc[0][0] = ffma2(a0, b0, acc[0][0]); acc[0][1] = ffma2(a0, b1, acc[0][1]);
            acc[0][2] = ffma2(a0, b2, acc[0][2]); acc[0][3] = ffma2(a0, b3, acc[0][3]);
            acc[1][0] = ffma2(a1, b0, acc[1][0]); acc[1][1] = ffma2(a1, b1, acc[1][1]);
            acc[1][2] = ffma2(a1, b2, acc[1][2]); acc[1][3] = ffma2(a1, b3, acc[1][3]);
            acc[2][0] = ffma2(a2, b0, acc[2][0]); acc[2][1] = ffma2(a2, b1, acc[2][1]);
            acc[2][2] = ffma2(a2, b2, acc[2][2]); acc[2][3] = ffma2(a2, b3, acc[2][3]);
            acc[3][0] = ffma2(a3, b0, acc[3][0]); acc[3][1] = ffma2(a3, b1, acc[3][1]);
            acc[3][2] = ffma2(a3, b2, acc[3][2]); acc[3][3] = ffma2(a3, b3, acc[3][3]);
        }
        __syncthreads();   // everyone done reading sX before we overwrite with H

        // ---- bias + t[vx] + relu, store H transposed into sX ----
        #pragma unroll
        for (int jj = 0; jj < 4; jj++) {
            int jlo = jb + 2 * jj, jhi = jlo + 1;
            float blo = sB1[jlo], bhi = sB1[jhi];
            #pragma unroll
            for (int i = 0; i < 4; i++) {
                int r = r0 + i;
                float lo, hi; unp2(acc[i][jj], lo, hi);
                if (right) {
                    int vv = sVx[r];
                    lo += sT[vv * 64 + (jlo - 64)];
                    hi += sT[vv * 64 + (jhi - 64)];
                }
                sX[jlo * LDA + r] = fmaxf(lo + blo, 0.f);
                sX[jhi * LDA + r] = fmaxf(hi + bhi, 0.f);
            }
        }
        __syncthreads();

        // ---- GEMM2: h_left @ cn_W2 (cols 0..63) / h_right @ bn_W2 (cols 64..127) ----
        u64 acc2[4][4];
        #pragma unroll
        for (int i = 0; i < 4; i++)
            #pragma unroll
            for (int jj = 0; jj < 4; jj++) acc2[i][jj] = 0ull;

        const float* w2 = sW2 + (right ? 4096 : 0);
        const int jl = right ? (jb - 64) : jb;
        const float* hbase = sX + (right ? 64 * LDA : 0);

        #pragma unroll 4
        for (int k = 0; k < 64; k++) {
            const float* xk = hbase + k * LDA + r0;
            u64 a0 = dup2(xk[0]), a1 = dup2(xk[1]), a2 = dup2(xk[2]), a3 = dup2(xk[3]);
            const u64* wr = (const u64*)(w2 + k * 64 + jl);
            u64 b0 = wr[0], b1 = wr[1], b2 = wr[2], b3 = wr[3];
            acc2[0][0] = ffma2(a0, b0, acc2[0][0]); acc2[0][1] = ffma2(a0, b1, acc2[0][1]);
            acc2[0][2] = ffma2(a0, b2, acc2[0][2]); acc2[0][3] = ffma2(a0, b3, acc2[0][3]);
            acc2[1][0] = ffma2(a1, b0, acc2[1][0]); acc2[1][1] = ffma2(a1, b1, acc2[1][1]);
            acc2[1][2] = ffma2(a1, b2, acc2[1][2]); acc2[1][3] = ffma2(a1, b3, acc2[1][3]);
            acc2[2][0] = ffma2(a2, b0, acc2[2][0]); acc2[2][1] = ffma2(a2, b1, acc2[2][1]);
            acc2[2][2] = ffma2(a2, b2, acc2[2][2]); acc2[2][3] = ffma2(a2, b3, acc2[2][3]);
            acc2[3][0] = ffma2(a3, b0, acc2[3][0]); acc2[3][1] = ffma2(a3, b1, acc2[3][1]);
            acc2[3][2] = ffma2(a3, b2, acc2[3][2]); acc2[3][3] = ffma2(a3, b3, acc2[3][3]);
        }

        // ---- add b2, store e' (contiguous: pair row = [left|right]) + stage out tile ----
        float* ep = g_e[dst] + (size_t)b * (N_ * 64) + (size_t)j0 * 128;
        #pragma unroll
        for (int i = 0; i < 4; i++) {
            int r = r0 + i;
            float o[8];
            #pragma unroll
            for (int jj = 0; jj < 4; jj++) {
                unp2(acc2[i][jj], o[2 * jj], o[2 * jj + 1]);
                o[2 * jj]     += sB2[jb + 2 * jj];
                o[2 * jj + 1] += sB2[jb + 2 * jj + 1];
            }
            float4 v0 = make_float4(o[0], o[1], o[2], o[3]);
            float4 v1 = make_float4(o[4], o[5], o[6], o[7]);
            *(float4*)(ep + (size_t)r * 128 + jb)     = v0;
            *(float4*)(ep + (size_t)r * 128 + jb + 4) = v1;
            *(float4*)(sO + r * LDO + jb)     = v0;
            *(float4*)(sO + r * LDO + jb + 4) = v1;
        }
        __syncthreads();

        // ---- fused head: softmax / loss / norm + v' write ----
        if (tid < 128) {
            int r = tid >> 1, c = tid & 1;
            int p = ((j0 + r) << 1) | c;
            unsigned char vp = c ? sVe[r] : sVx[r];
            g_v[dst][b * N_ + p] = vp;
            const float* er = sO + r * LDO + c * 64;
            float l0 = sLb[0], l1 = sLb[1], nr = 0.f;
            #pragma unroll
            for (int d4 = 0; d4 < 16; d4++) {
                float4 ev = *(const float4*)(er + 4 * d4);
                const float* w = sLW + 8 * d4;
                l0 += ev.x * w[0] + ev.y * w[2] + ev.z * w[4] + ev.w * w[6];
                l1 += ev.x * w[1] + ev.y * w[3] + ev.z * w[5] + ev.w * w[7];
                nr += ev.x * ev.x + ev.y * ev.y + ev.z * ev.z + ev.w * ev.w;
            }
            float m = fmaxf(l0, l1);
            float x0 = expf(l0 - m), x1 = expf(l1 - m);
            float inv = 1.f / (x0 + x1);
            float p0 = x0 * inv, p1 = x1 * inv;
            float pt = vp ? p1 : p0;
            float loss = -logf(fminf(fmaxf(pt, 1e-7f), 1.f));
            out[(size_t)b * (11 * N_) + (size_t)s * N_ + p] = loss;
            float* pr = out + PRED_OFF + (((size_t)(b * N_ + p)) * 11 + s) * 2;
            pr[0] = p0; pr[1] = p1;
            out[NORM_OFF + (size_t)b * (11 * N_) + (size_t)s * N_ + p] = sqrtf(nr);
        }
        __syncthreads();   // protect sX/sVx/sO before next tile
    }
}

// ---------------- launch ----------------
extern "C" void kernel_launch(void* const* d_in, const int* in_sizes, int n_in,
                              void* d_out, int out_size) {
    const int*   x    = (const int*)d_in[0];
    const float* y    = (const float*)d_in[1];
    const float* embW = (const float*)d_in[2];
    const float* embb = (const float*)d_in[3];
    const float* lab  = (const float*)d_in[4];
    const float* cnW1 = (const float*)d_in[5];
    const float* cnb1 = (const float*)d_in[6];
    const float* cnW2 = (const float*)d_in[7];
    const float* cnb2 = (const float*)d_in[8];
    const float* bnW1 = (const float*)d_in[9];
    const float* bnb1 = (const float*)d_in[10];
    const float* bnW2 = (const float*)d_in[11];
    const float* bnb2 = (const float*)d_in[12];
    const float* llrW = (const float*)d_in[13];
    const float* llrb = (const float*)d_in[14];
    float* out = (float*)d_out;

    cudaFuncSetAttribute(stage_kernel, cudaFuncAttributeMaxDynamicSharedMemorySize, SMEM_BYTES);

    prep_kernel<<<1, 256>>>(cnW1, bnW1, cnW2, bnW2, cnb1, bnb1, cnb2, bnb2, lab);
    stage0_kernel<<<1024, 256>>>(x, y, embW, embb);
    head0_kernel<<<(B_ * N_ * 32) / 256, 256>>>(llrW, llrb, out);
    for (int s = 1; s <= 10; s++) {
        stage_kernel<<<152, 256, SMEM_BYTES>>>(1 << s, (s - 1) & 1, s, llrW, llrb, out);
    }
}

// round 3
// speedup vs baseline: 1.6473x; 1.6473x over previous
#include <cuda_runtime.h>

#define B_ 256
#define N_ 1024
#define NPAIR 512
#define NT 1024              // tiles of 128 pairs
#define LDA 132

#define PRED_OFF (B_*11*N_)                  // 2883584
#define NORM_OFF (PRED_OFF + B_*N_*11*2)     // 8650752

typedef unsigned long long u64;

// ---------------- persistent device scratch ----------------
__device__ float g_e[2][(size_t)B_ * N_ * 64];
__device__ unsigned char g_v[2][B_ * N_];
__device__ float g_W1[128 * 128];      // fused first-layer weight [k][j]; j<64 cn, j>=64 bn
__device__ float g_W2[2 * 64 * 64];    // [0]=cn_W2, [1]=bn_W2, each [k][j]
__device__ float g_B1[128];
__device__ float g_B2[128];
__device__ float g_T[2 * 64];          // lab_emb[v] @ bn_W1[128:192,:]

// ---------------- f32x2 helpers ----------------
__device__ __forceinline__ u64 dup2(float v) {
    u64 r; asm("mov.b64 %0, {%1,%1};" : "=l"(r) : "f"(v)); return r;
}
__device__ __forceinline__ void unp2(u64 p, float& lo, float& hi) {
    asm("mov.b64 {%0,%1}, %2;" : "=f"(lo), "=f"(hi) : "l"(p));
}
__device__ __forceinline__ u64 ffma2(u64 a, u64 b, u64 c) {
    u64 d; asm("fma.rn.f32x2 %0, %1, %2, %3;" : "=l"(d) : "l"(a), "l"(b), "l"(c)); return d;
}

// ---------------- weight preprocessing ----------------
__global__ void prep_kernel(const float* cnW1, const float* bnW1,
                            const float* cnW2, const float* bnW2,
                            const float* cnb1, const float* bnb1,
                            const float* cnb2, const float* bnb2,
                            const float* lab) {
    int t = threadIdx.x;
    for (int i = t; i < 128 * 128; i += 256) {
        int k = i >> 7, j = i & 127;
        g_W1[i] = (j < 64) ? cnW1[k * 64 + j] : bnW1[k * 64 + (j - 64)];
    }
    for (int i = t; i < 4096; i += 256) {
        g_W2[i] = cnW2[i];
        g_W2[4096 + i] = bnW2[i];
    }
    if (t < 64) {
        g_B1[t] = cnb1[t]; g_B1[64 + t] = bnb1[t];
        g_B2[t] = cnb2[t]; g_B2[64 + t] = bnb2[t];
    }
    if (t < 128) {
        int v = t >> 6, j = t & 63;
        float s = 0.f;
        for (int m = 0; m < 64; m++) s += lab[v * 64 + m] * bnW1[(128 + m) * 64 + j];
        g_T[t] = s;
    }
}

// ---------------- stage 0: embedding + fused head ----------------
__global__ void stage0_kernel(const int* __restrict__ x, const float* __restrict__ y,
                              const float* __restrict__ embW, const float* __restrict__ embb,
                              const float* __restrict__ llrW, const float* __restrict__ llrb,
                              float* __restrict__ out) {
    int f = blockIdx.x * blockDim.x + threadIdx.x;   // 0 .. B*N*16-1
    int pos = f >> 4;
    int c4 = (f & 15) << 2;
    float y0 = y[pos * 2 + 0], y1 = y[pos * 2 + 1];
    float4 w0 = *(const float4*)(embW + c4);
    float4 w1 = *(const float4*)(embW + 64 + c4);
    float4 bb = *(const float4*)(embb + c4);
    float4 e;
    e.x = fmaf(y0, w0.x, fmaf(y1, w1.x, bb.x));
    e.y = fmaf(y0, w0.y, fmaf(y1, w1.y, bb.y));
    e.z = fmaf(y0, w0.z, fmaf(y1, w1.z, bb.z));
    e.w = fmaf(y0, w0.w, fmaf(y1, w1.w, bb.w));
    *(float4*)(&g_e[0][(size_t)pos * 64 + c4]) = e;

    // head partials: llrW is [64][2]
    float4 wa = *(const float4*)(llrW + c4 * 2);       // dims c4, c4+1
    float4 wb = *(const float4*)(llrW + c4 * 2 + 4);   // dims c4+2, c4+3
    float l0 = e.x * wa.x + e.y * wa.z + e.z * wb.x + e.w * wb.z;
    float l1 = e.x * wa.y + e.y * wa.w + e.z * wb.y + e.w * wb.w;
    float nr = e.x * e.x + e.y * e.y + e.z * e.z + e.w * e.w;
    #pragma unroll
    for (int o = 8; o >= 1; o >>= 1) {
        l0 += __shfl_xor_sync(0xffffffffu, l0, o);
        l1 += __shfl_xor_sync(0xffffffffu, l1, o);
        nr += __shfl_xor_sync(0xffffffffu, nr, o);
    }
    if ((f & 15) == 0) {
        int v = x[pos];
        g_v[0][pos] = (unsigned char)v;
        l0 += llrb[0]; l1 += llrb[1];
        float m = fmaxf(l0, l1);
        float x0 = expf(l0 - m), x1 = expf(l1 - m);
        float inv = 1.f / (x0 + x1);
        float p0 = x0 * inv, p1 = x1 * inv;
        float pt = v ? p1 : p0;
        float loss = -logf(fminf(fmaxf(pt, 1e-7f), 1.f));
        int b = pos >> 10, p = pos & 1023;
        out[(size_t)b * (11 * N_) + p] = loss;
        float2* pr = (float2*)(out + PRED_OFF + (((size_t)(b * N_ + p)) * 11) * 2);
        *pr = make_float2(p0, p1);
        out[NORM_OFF + (size_t)b * (11 * N_) + p] = sqrtf(nr);
    }
}

// ---------------- main butterfly-stage kernel ----------------
// smem floats: W1 16384 | W2 8192 | X 16896 | T 128  = 41600 floats = 166400 B
#define OFF_W2 16384
#define OFF_X  24576
#define OFF_T  41472
#define SMEM_FLOATS 41600
#define SMEM_BYTES (SMEM_FLOATS * 4)

__global__ void __launch_bounds__(256, 1)
stage_kernel(int scope, int src, int s,
             const float* __restrict__ llrW, const float* __restrict__ llrb,
             float* __restrict__ out) {
    extern __shared__ float sm[];
    float* sW1 = sm;
    float* sW2 = sm + OFF_W2;
    float* sX  = sm + OFF_X;
    float* sT  = sm + OFF_T;
    __shared__ unsigned char sVx[128], sVe[128];

    int tid = threadIdx.x;
    {   // weight staging (float4 copies)
        const float4* src4 = (const float4*)g_W1;
        float4* dst4 = (float4*)sW1;
        #pragma unroll
        for (int i = 0; i < 16; i++) dst4[tid + i * 256] = src4[tid + i * 256];
        const float4* src2 = (const float4*)g_W2;
        float4* dst2 = (float4*)sW2;
        #pragma unroll
        for (int i = 0; i < 8; i++) dst2[tid + i * 256] = src2[tid + i * 256];
        if (tid < 128) sT[tid] = g_T[tid];
    }
    __syncthreads();

    const int half = scope >> 1;
    const int dst = src ^ 1;
    const int tx = tid & 15;
    const int ty = tid >> 4;         // 0..15
    const int r0 = ty * 8;
    const int jb = tx * 8;
    const bool right = (jb >= 64);
    const int jl = jb & 63;
    const float* w2 = sW2 + (right ? 4096 : 0);
    const int swzH = (tx & 7) << 2;

    // hoisted per-thread constants (llrW indexed by dim within the 64-wide head!)
    float b1r[8], b2r[8], lw0[8], lw1[8];
    #pragma unroll
    for (int q = 0; q < 8; q++) {
        b1r[q] = g_B1[jb + q];
        b2r[q] = g_B2[jb + q];
        int dim = (jb + q) & 63;
        lw0[q] = llrW[dim * 2];
        lw1[q] = llrW[dim * 2 + 1];
    }
    const float lb0 = llrb[0], lb1 = llrb[1];

    for (int tile = blockIdx.x; tile < NT; tile += gridDim.x) {
        int b  = tile >> 2;
        int j0 = (tile & 3) << 7;                // 128 pairs per tile
        const float* eb = g_e[src] + (size_t)b * (N_ * 64);
        const unsigned char* vb = g_v[src] + b * N_;

        // ---- bits ----
        if (tid < 128) {
            int j = j0 + tid;
            int so = ((j & ~(half - 1)) << 1) | (j & (half - 1));
            unsigned char vo = vb[so], ve = vb[so + half];
            sVx[tid] = (unsigned char)((vo + ve) & 1);
            sVe[tid] = ve;
        }
        // ---- gather 128 pairs x 128 dims, transposed k-major with XOR swizzle ----
        #pragma unroll
        for (int it = 0; it < 16; it++) {
            int c  = tid + it * 256;
            int rh = c >> 4;                  // 0..255
            int fq = c & 15;
            int r  = rh >> 1, hs = rh & 1;
            int j  = j0 + r;
            int so = ((j & ~(half - 1)) << 1) | (j & (half - 1));
            int srcpos = so + hs * half;
            float4 val = *(const float4*)(eb + (size_t)srcpos * 64 + fq * 4);
            int kb = hs * 64 + fq * 4;
            int rr = r ^ ((fq & 7) << 2);
            float* d = sX + kb * LDA + rr;
            d[0]       = val.x;
            d[LDA]     = val.y;
            d[2 * LDA] = val.z;
            d[3 * LDA] = val.w;
        }
        __syncthreads();

        // ---- GEMM1: [128 x 128] @ [128 x 128], 8x8 per thread ----
        u64 acc[8][4];
        #pragma unroll
        for (int i = 0; i < 8; i++)
            #pragma unroll
            for (int jj = 0; jj < 4; jj++) acc[i][jj] = 0ull;

        #pragma unroll 4
        for (int k = 0; k < 128; k++) {
            int swz = ((k >> 2) & 7) << 2;
            const float* xr = sX + k * LDA;
            int ra = r0 ^ swz;
            float4 a03 = *(const float4*)(xr + ra);
            float4 a47 = *(const float4*)(xr + (ra ^ 4));
            const u64* wr = (const u64*)(sW1 + k * 128 + jb);
            u64 wb0 = wr[0], wb1 = wr[1], wb2 = wr[2], wb3 = wr[3];
            u64 a[8];
            a[0] = dup2(a03.x); a[1] = dup2(a03.y); a[2] = dup2(a03.z); a[3] = dup2(a03.w);
            a[4] = dup2(a47.x); a[5] = dup2(a47.y); a[6] = dup2(a47.z); a[7] = dup2(a47.w);
            #pragma unroll
            for (int i = 0; i < 8; i++) {
                acc[i][0] = ffma2(a[i], wb0, acc[i][0]);
                acc[i][1] = ffma2(a[i], wb1, acc[i][1]);
                acc[i][2] = ffma2(a[i], wb2, acc[i][2]);
                acc[i][3] = ffma2(a[i], wb3, acc[i][3]);
            }
        }
        __syncthreads();   // done reading X before overwriting with H

        // ---- epilogue1: bias + t[vx] + relu, store H (swizzled, per-column float4) ----
        #pragma unroll
        for (int jj = 0; jj < 4; jj++) {
            int q0 = 2 * jj, q1 = q0 + 1;
            int jlo = jb + q0, jhi = jb + q1;
            float h0[8], h1[8];
            #pragma unroll
            for (int i = 0; i < 8; i++) {
                float lo, hi; unp2(acc[i][jj], lo, hi);
                if (right) {
                    int vv = sVx[r0 + i];
                    lo += sT[vv * 64 + (jlo - 64)];
                    hi += sT[vv * 64 + (jhi - 64)];
                }
                h0[i] = fmaxf(lo + b1r[q0], 0.f);
                h1[i] = fmaxf(hi + b1r[q1], 0.f);
            }
            int rr = r0 ^ swzH;
            *(float4*)(sX + jlo * LDA + rr)       = make_float4(h0[0], h0[1], h0[2], h0[3]);
            *(float4*)(sX + jlo * LDA + (rr ^ 4)) = make_float4(h0[4], h0[5], h0[6], h0[7]);
            *(float4*)(sX + jhi * LDA + rr)       = make_float4(h1[0], h1[1], h1[2], h1[3]);
            *(float4*)(sX + jhi * LDA + (rr ^ 4)) = make_float4(h1[4], h1[5], h1[6], h1[7]);
        }
        __syncthreads();

        // ---- GEMM2: [128 x 64] @ [64 x 64] per half ----
        u64 acc2[8][4];
        #pragma unroll
        for (int i = 0; i < 8; i++)
            #pragma unroll
            for (int jj = 0; jj < 4; jj++) acc2[i][jj] = 0ull;

        const float* hb = sX + (right ? 64 * LDA : 0);
        #pragma unroll 4
        for (int k = 0; k < 64; k++) {
            int swz = ((k >> 3) & 7) << 2;
            const float* xr = hb + k * LDA;
            int ra = r0 ^ swz;
            float4 a03 = *(const float4*)(xr + ra);
            float4 a47 = *(const float4*)(xr + (ra ^ 4));
            const u64* wr = (const u64*)(w2 + k * 64 + jl);
            u64 wb0 = wr[0], wb1 = wr[1], wb2 = wr[2], wb3 = wr[3];
            u64 a[8];
            a[0] = dup2(a03.x); a[1] = dup2(a03.y); a[2] = dup2(a03.z); a[3] = dup2(a03.w);
            a[4] = dup2(a47.x); a[5] = dup2(a47.y); a[6] = dup2(a47.z); a[7] = dup2(a47.w);
            #pragma unroll
            for (int i = 0; i < 8; i++) {
                acc2[i][0] = ffma2(a[i], wb0, acc2[i][0]);
                acc2[i][1] = ffma2(a[i], wb1, acc2[i][1]);
                acc2[i][2] = ffma2(a[i], wb2, acc2[i][2]);
                acc2[i][3] = ffma2(a[i], wb3, acc2[i][3]);
            }
        }

        // ---- epilogue2: bias + e' store + head partials ----
        float L0[8], L1[8], NR[8];
        float* ep = g_e[dst] + (size_t)b * (N_ * 64) + (size_t)j0 * 128;
        #pragma unroll
        for (int i = 0; i < 8; i++) {
            float o[8];
            #pragma unroll
            for (int jj = 0; jj < 4; jj++) unp2(acc2[i][jj], o[2 * jj], o[2 * jj + 1]);
            #pragma unroll
            for (int q = 0; q < 8; q++) o[q] += b2r[q];
            float* row = ep + (size_t)(r0 + i) * 128 + jb;
            *(float4*)(row)     = make_float4(o[0], o[1], o[2], o[3]);
            *(float4*)(row + 4) = make_float4(o[4], o[5], o[6], o[7]);
            float l0 = 0.f, l1 = 0.f, nr = 0.f;
            #pragma unroll
            for (int q = 0; q < 8; q++) {
                l0 += o[q] * lw0[q];
                l1 += o[q] * lw1[q];
                nr += o[q] * o[q];
            }
            L0[i] = l0; L1[i] = l1; NR[i] = nr;
        }
        // reduce across the 8 lanes covering one side of each row
        #pragma unroll
        for (int off = 4; off >= 1; off >>= 1) {
            #pragma unroll
            for (int i = 0; i < 8; i++) {
                L0[i] += __shfl_xor_sync(0xffffffffu, L0[i], off);
                L1[i] += __shfl_xor_sync(0xffffffffu, L1[i], off);
                NR[i] += __shfl_xor_sync(0xffffffffu, NR[i], off);
            }
        }
        if ((tx & 7) == 0) {
            int cside = tx >> 3;   // 0 = left (even positions), 1 = right (odd)
            #pragma unroll
            for (int i = 0; i < 8; i++) {
                int r = r0 + i;
                int p = ((j0 + r) << 1) | cside;
                unsigned char vp = cside ? sVe[r] : sVx[r];
                g_v[dst][b * N_ + p] = vp;
                float l0 = L0[i] + lb0, l1 = L1[i] + lb1;
                float m = fmaxf(l0, l1);
                float x0 = expf(l0 - m), x1 = expf(l1 - m);
                float inv = 1.f / (x0 + x1);
                float p0 = x0 * inv, p1 = x1 * inv;
                float pt = vp ? p1 : p0;
                float loss = -logf(fminf(fmaxf(pt, 1e-7f), 1.f));
                out[(size_t)b * (11 * N_) + (size_t)s * N_ + p] = loss;
                float2* pr = (float2*)(out + PRED_OFF + (((size_t)(b * N_ + p)) * 11 + s) * 2);
                *pr = make_float2(p0, p1);
                out[NORM_OFF + (size_t)b * (11 * N_) + (size_t)s * N_ + p] = sqrtf(NR[i]);
            }
        }
        __syncthreads();   // protect sX / sVx / sVe before next tile
    }
}

// ---------------- launch ----------------
extern "C" void kernel_launch(void* const* d_in, const int* in_sizes, int n_in,
                              void* d_out, int out_size) {
    const int*   x    = (const int*)d_in[0];
    const float* y    = (const float*)d_in[1];
    const float* embW = (const float*)d_in[2];
    const float* embb = (const float*)d_in[3];
    const float* lab  = (const float*)d_in[4];
    const float* cnW1 = (const float*)d_in[5];
    const float* cnb1 = (const float*)d_in[6];
    const float* cnW2 = (const float*)d_in[7];
    const float* cnb2 = (const float*)d_in[8];
    const float* bnW1 = (const float*)d_in[9];
    const float* bnb1 = (const float*)d_in[10];
    const float* bnW2 = (const float*)d_in[11];
    const float* bnb2 = (const float*)d_in[12];
    const float* llrW = (const float*)d_in[13];
    const float* llrb = (const float*)d_in[14];
    float* out = (float*)d_out;

    cudaFuncSetAttribute(stage_kernel, cudaFuncAttributeMaxDynamicSharedMemorySize, SMEM_BYTES);

    prep_kernel<<<1, 256>>>(cnW1, bnW1, cnW2, bnW2, cnb1, bnb1, cnb2, bnb2, lab);
    stage0_kernel<<<(B_ * N_ * 16) / 256, 256>>>(x, y, embW, embb, llrW, llrb, out);
    for (int s = 1; s <= 10; s++) {
        stage_kernel<<<152, 256, SMEM_BYTES>>>(1 << s, (s - 1) & 1, s, llrW, llrb, out);
    }
}

// round 5
// speedup vs baseline: 3.3793x; 2.0515x over previous
#include <cuda_runtime.h>
#include <cuda_bf16.h>

#define B_ 256
#define N_ 1024
#define NT 1024              // tiles of 128 pairs

#define PRED_OFF (B_*11*N_)                  // 2883584
#define NORM_OFF (PRED_OFF + B_*N_*11*2)     // 8650752

#define SX 136               // bf16 stride for X/H and W1 tiles (272B rows)
#define SW 72                // bf16 stride for W2 tiles (144B rows)

// smem byte offsets
#define OXHI 0
#define OXLO 34816
#define OW1H 69632
#define OW1L 104448
#define OW2  139264          // 4 x 9216: cn_hi, cn_lo, bn_hi, bn_lo
#define OT   176128
#define OB1  176640
#define OB2  177152
#define OLW  177664
#define DSMEM_BYTES 178176

typedef unsigned long long u64;
typedef unsigned int u32;

// ---------------- persistent device scratch ----------------
__device__ __align__(16) float g_e[2][(size_t)B_ * N_ * 64];
__device__ unsigned char g_v[2][B_ * N_];
__device__ __align__(16) __nv_bfloat16 g_W1hi[16384];   // W1T fused [j=128][k=128]
__device__ __align__(16) __nv_bfloat16 g_W1lo[16384];
__device__ __align__(16) __nv_bfloat16 g_W2i[4][4096];  // cn_hi, cn_lo, bn_hi, bn_lo [j=64][k=64]
__device__ float g_B1[128], g_B2[128], g_T[128];

// ---------------- helpers ----------------
__device__ __forceinline__ u32 smem_u32(const void* p) {
    u32 a; asm("{ .reg .u64 t; cvta.to.shared.u64 t, %1; cvt.u32.u64 %0, t; }" : "=r"(a) : "l"(p));
    return a;
}
__device__ __forceinline__ void ldsm4(u32 addr, u32& r0, u32& r1, u32& r2, u32& r3) {
    asm volatile("ldmatrix.sync.aligned.m8n8.x4.shared.b16 {%0,%1,%2,%3}, [%4];"
        : "=r"(r0), "=r"(r1), "=r"(r2), "=r"(r3) : "r"(addr));
}
__device__ __forceinline__ void mma16816(float* c, const u32* a, u32 b0, u32 b1) {
    asm volatile("mma.sync.aligned.m16n8k16.row.col.f32.bf16.bf16.f32 "
        "{%0,%1,%2,%3}, {%4,%5,%6,%7}, {%8,%9}, {%0,%1,%2,%3};"
        : "+f"(c[0]), "+f"(c[1]), "+f"(c[2]), "+f"(c[3])
        : "r"(a[0]), "r"(a[1]), "r"(a[2]), "r"(a[3]), "r"(b0), "r"(b1));
}
__device__ __forceinline__ u32 pkhi(float a, float b, u32& lopk) {
    __nv_bfloat16 ha = __float2bfloat16(a), hb = __float2bfloat16(b);
    __nv_bfloat16 la = __float2bfloat16(a - __bfloat162float(ha));
    __nv_bfloat16 lb = __float2bfloat16(b - __bfloat162float(hb));
    __nv_bfloat162 H = __halves2bfloat162(ha, hb), L = __halves2bfloat162(la, lb);
    lopk = *(u32*)&L;
    return *(u32*)&H;
}

// ---------------- weight preprocessing ----------------
__global__ void prep_kernel(const float* cnW1, const float* bnW1,
                            const float* cnW2, const float* bnW2,
                            const float* cnb1, const float* bnb1,
                            const float* cnb2, const float* bnb2,
                            const float* lab) {
    int t = threadIdx.x;
    for (int i = t; i < 128 * 128; i += 256) {
        int j = i >> 7, k = i & 127;        // [j][k] transposed image
        float a = (j < 64) ? cnW1[k * 64 + j] : bnW1[k * 64 + (j - 64)];
        __nv_bfloat16 h = __float2bfloat16(a);
        g_W1hi[i] = h;
        g_W1lo[i] = __float2bfloat16(a - __bfloat162float(h));
    }
    for (int i = t; i < 4096; i += 256) {
        int j = i >> 6, k = i & 63;
        float a = cnW2[k * 64 + j];
        __nv_bfloat16 h = __float2bfloat16(a);
        g_W2i[0][i] = h;
        g_W2i[1][i] = __float2bfloat16(a - __bfloat162float(h));
        float bnv = bnW2[k * 64 + j];
        __nv_bfloat16 hb = __float2bfloat16(bnv);
        g_W2i[2][i] = hb;
        g_W2i[3][i] = __float2bfloat16(bnv - __bfloat162float(hb));
    }
    if (t < 64) {
        g_B1[t] = cnb1[t]; g_B1[64 + t] = bnb1[t];
        g_B2[t] = cnb2[t]; g_B2[64 + t] = bnb2[t];
    }
    if (t < 128) {
        int v = t >> 6, j = t & 63;
        float s = 0.f;
        for (int m = 0; m < 64; m++) s += lab[v * 64 + m] * bnW1[(128 + m) * 64 + j];
        g_T[t] = s;
    }
}

// ---------------- stage 0: embedding + fused head ----------------
__global__ void stage0_kernel(const int* __restrict__ x, const float* __restrict__ y,
                              const float* __restrict__ embW, const float* __restrict__ embb,
                              const float* __restrict__ llrW, const float* __restrict__ llrb,
                              float* __restrict__ out) {
    int f = blockIdx.x * blockDim.x + threadIdx.x;
    int pos = f >> 4;
    int c4 = (f & 15) << 2;
    float y0 = y[pos * 2 + 0], y1 = y[pos * 2 + 1];
    float4 w0 = *(const float4*)(embW + c4);
    float4 w1 = *(const float4*)(embW + 64 + c4);
    float4 bb = *(const float4*)(embb + c4);
    float4 e;
    e.x = fmaf(y0, w0.x, fmaf(y1, w1.x, bb.x));
    e.y = fmaf(y0, w0.y, fmaf(y1, w1.y, bb.y));
    e.z = fmaf(y0, w0.z, fmaf(y1, w1.z, bb.z));
    e.w = fmaf(y0, w0.w, fmaf(y1, w1.w, bb.w));
    *(float4*)(&g_e[0][(size_t)pos * 64 + c4]) = e;

    float4 wa = *(const float4*)(llrW + c4 * 2);
    float4 wb = *(const float4*)(llrW + c4 * 2 + 4);
    float l0 = e.x * wa.x + e.y * wa.z + e.z * wb.x + e.w * wb.z;
    float l1 = e.x * wa.y + e.y * wa.w + e.z * wb.y + e.w * wb.w;
    float nr = e.x * e.x + e.y * e.y + e.z * e.z + e.w * e.w;
    #pragma unroll
    for (int o = 8; o >= 1; o >>= 1) {
        l0 += __shfl_xor_sync(0xffffffffu, l0, o);
        l1 += __shfl_xor_sync(0xffffffffu, l1, o);
        nr += __shfl_xor_sync(0xffffffffu, nr, o);
    }
    if ((f & 15) == 0) {
        int v = x[pos];
        g_v[0][pos] = (unsigned char)v;
        l0 += llrb[0]; l1 += llrb[1];
        float m = fmaxf(l0, l1);
        float x0 = expf(l0 - m), x1 = expf(l1 - m);
        float inv = 1.f / (x0 + x1);
        float p0 = x0 * inv, p1 = x1 * inv;
        float pt = v ? p1 : p0;
        float loss = -logf(fminf(fmaxf(pt, 1e-7f), 1.f));
        int b = pos >> 10, p = pos & 1023;
        out[(size_t)b * (11 * N_) + p] = loss;
        float2* pr = (float2*)(out + PRED_OFF + (((size_t)(b * N_ + p)) * 11) * 2);
        *pr = make_float2(p0, p1);
        out[NORM_OFF + (size_t)b * (11 * N_) + p] = sqrtf(nr);
    }
}

// ---------------- main butterfly-stage kernel (warp mma.sync bf16) ----------------
__global__ void __launch_bounds__(256, 1)
stage_kernel(int scope, int src, int s,
             const float* __restrict__ llrW, const float* __restrict__ llrb,
             float* __restrict__ out) {
    extern __shared__ char smp[];
    const u32 smb = smem_u32(smp);
    float* sT  = (float*)(smp + OT);
    float* sB1 = (float*)(smp + OB1);
    float* sB2 = (float*)(smp + OB2);
    float* sLW = (float*)(smp + OLW);
    __shared__ unsigned char sVx[128], sVe[128];

    const int tid = threadIdx.x;

    {   // stage weights: W1 hi/lo and W2 into padded smem layouts
        #pragma unroll
        for (int it = 0; it < 8; it++) {
            int i = tid + it * 256;          // 2048 uint4 per buffer
            int j = i >> 4, c = i & 15;
            uint4 v1 = ((const uint4*)g_W1hi)[i];
            uint4 v2 = ((const uint4*)g_W1lo)[i];
            *(uint4*)(smp + OW1H + j * (SX * 2) + c * 16) = v1;
            *(uint4*)(smp + OW1L + j * (SX * 2) + c * 16) = v2;
            // W2: 2048 uint4 total (4 mats x 64 rows x 8 chunks)
            int mt = i >> 9, rem = i & 511;
            int j2 = rem >> 3, c2 = rem & 7;
            uint4 v3 = ((const uint4*)g_W2i)[mt * 512 + j2 * 8 + c2];
            *(uint4*)(smp + OW2 + mt * 9216 + j2 * (SW * 2) + c2 * 16) = v3;
        }
        if (tid < 128) { sT[tid] = g_T[tid]; sB1[tid] = g_B1[tid]; sB2[tid] = g_B2[tid]; sLW[tid] = llrW[tid]; }
    }
    __syncthreads();

    const int half = scope >> 1;
    const int dst = src ^ 1;
    const int w = tid >> 5, l = tid & 31;
    const int wm = w & 3, wn = w >> 2;       // 4m x 2n warp grid
    const int m0 = wm * 32;
    const int n0 = wn * 64;
    const int side = wn;
    const float lb0 = llrb[0], lb1 = llrb[1];

    // ldmatrix per-thread address components (byte offsets)
    const int aoff = (m0 + (l & 15)) * (SX * 2) + ((l >> 4) << 3) * 2;          // A frag, GEMM1
    const int boff1 = ((l & 7) + ((l >> 1) & 8) + n0) * (SX * 2) + (l & 8) * 2; // B frag, GEMM1 (row j)
    const int aoff2 = (m0 + (l & 15)) * (SX * 2) + (side * 64 + ((l >> 4) << 3)) * 2;
    const int boff2 = ((l & 7) + ((l >> 1) & 8)) * (SW * 2) + (l & 8) * 2;
    const u32 w2hiB = smb + OW2 + side * 18432;

    for (int tile = blockIdx.x; tile < NT; tile += gridDim.x) {
        int b  = tile >> 2;
        int j0 = (tile & 3) << 7;
        const float* eb = g_e[src] + (size_t)b * (N_ * 64);
        const unsigned char* vb = g_v[src] + b * N_;

        // ---- bits ----
        if (tid < 128) {
            int j = j0 + tid;
            int so = ((j & ~(half - 1)) << 1) | (j & (half - 1));
            unsigned char vo = vb[so], ve = vb[so + half];
            sVx[tid] = (unsigned char)((vo + ve) & 1);
            sVe[tid] = ve;
        }
        // ---- gather X (128 pairs x 128 dims) as bf16 hi/lo ----
        #pragma unroll
        for (int it = 0; it < 8; it++) {
            int c  = tid + (it << 8);
            int r  = c >> 4;
            int f8 = c & 15;
            int hs = f8 >> 3;
            int j  = j0 + r;
            int so = ((j & ~(half - 1)) << 1) | (j & (half - 1));
            const float* p = eb + (size_t)(so + hs * half) * 64 + ((f8 & 7) << 3);
            float4 v0 = *(const float4*)p;
            float4 v1 = *(const float4*)(p + 4);
            uint4 H, L;
            H.x = pkhi(v0.x, v0.y, L.x); H.y = pkhi(v0.z, v0.w, L.y);
            H.z = pkhi(v1.x, v1.y, L.z); H.w = pkhi(v1.z, v1.w, L.w);
            int ad = r * (SX * 2) + f8 * 16;
            *(uint4*)(smp + OXHI + ad) = H;
            *(uint4*)(smp + OXLO + ad) = L;
        }
        __syncthreads();

        // ---- GEMM1: C[128x128] = X @ W1T^T, 3-term bf16 split ----
        float acc[2][8][4];
        #pragma unroll
        for (int mt = 0; mt < 2; mt++)
            #pragma unroll
            for (int nt = 0; nt < 8; nt++)
                #pragma unroll
                for (int q = 0; q < 4; q++) acc[mt][nt][q] = 0.f;

        #pragma unroll
        for (int kc = 0; kc < 8; kc++) {
            int kb = kc * 32;   // byte offset of k0 = kc*16 bf16
            u32 ah[2][4], al[2][4];
            #pragma unroll
            for (int mt = 0; mt < 2; mt++) {
                ldsm4(smb + OXHI + aoff + mt * 16 * (SX * 2) + kb, ah[mt][0], ah[mt][1], ah[mt][2], ah[mt][3]);
                ldsm4(smb + OXLO + aoff + mt * 16 * (SX * 2) + kb, al[mt][0], al[mt][1], al[mt][2], al[mt][3]);
            }
            #pragma unroll
            for (int np = 0; np < 4; np++) {
                u32 bh[4], bl[4];
                ldsm4(smb + OW1H + boff1 + np * 16 * (SX * 2) + kb, bh[0], bh[1], bh[2], bh[3]);
                ldsm4(smb + OW1L + boff1 + np * 16 * (SX * 2) + kb, bl[0], bl[1], bl[2], bl[3]);
                #pragma unroll
                for (int mt = 0; mt < 2; mt++) {
                    #pragma unroll
                    for (int hh = 0; hh < 2; hh++) {
                        float* c = acc[mt][np * 2 + hh];
                        mma16816(c, ah[mt], bh[2 * hh], bh[2 * hh + 1]);
                        mma16816(c, ah[mt], bl[2 * hh], bl[2 * hh + 1]);
                        mma16816(c, al[mt], bh[2 * hh], bh[2 * hh + 1]);
                    }
                }
            }
        }
        __syncthreads();   // all reads of X done before H overwrites it

        // ---- epilogue1: h = relu(C + b1 + T[vx]) -> H bf16 hi/lo into X buffer ----
        {
            #pragma unroll
            for (int mt = 0; mt < 2; mt++) {
                int rowa = m0 + mt * 16 + (l >> 2);
                int rowb = rowa + 8;
                int va = sVx[rowa], vbt = sVx[rowb];
                #pragma unroll
                for (int nt = 0; nt < 8; nt++) {
                    float* c = acc[mt][nt];
                    int col = n0 + nt * 8 + (l & 3) * 2;
                    float b0 = sB1[col], b1v = sB1[col + 1];
                    float v00 = c[0] + b0, v01 = c[1] + b1v;
                    float v10 = c[2] + b0, v11 = c[3] + b1v;
                    if (side) {
                        int tcol = col - 64;
                        v00 += sT[va * 64 + tcol];  v01 += sT[va * 64 + tcol + 1];
                        v10 += sT[vbt * 64 + tcol]; v11 += sT[vbt * 64 + tcol + 1];
                    }
                    v00 = fmaxf(v00, 0.f); v01 = fmaxf(v01, 0.f);
                    v10 = fmaxf(v10, 0.f); v11 = fmaxf(v11, 0.f);
                    u32 lo0, lo1;
                    u32 hi0 = pkhi(v00, v01, lo0);
                    u32 hi1 = pkhi(v10, v11, lo1);
                    int ada = rowa * (SX * 2) + col * 2;
                    int adb = rowb * (SX * 2) + col * 2;
                    *(u32*)(smp + OXHI + ada) = hi0;
                    *(u32*)(smp + OXLO + ada) = lo0;
                    *(u32*)(smp + OXHI + adb) = hi1;
                    *(u32*)(smp + OXLO + adb) = lo1;
                }
            }
        }
        __syncthreads();

        // ---- GEMM2: per side [128x64] = H_side @ W2_side, 3-term split ----
        float acc2[2][8][4];
        #pragma unroll
        for (int mt = 0; mt < 2; mt++)
            #pragma unroll
            for (int nt = 0; nt < 8; nt++)
                #pragma unroll
                for (int q = 0; q < 4; q++) acc2[mt][nt][q] = 0.f;

        #pragma unroll
        for (int kc = 0; kc < 4; kc++) {
            int kb = kc * 32;
            u32 ah[2][4], al[2][4];
            #pragma unroll
            for (int mt = 0; mt < 2; mt++) {
                ldsm4(smb + OXHI + aoff2 + mt * 16 * (SX * 2) + kb, ah[mt][0], ah[mt][1], ah[mt][2], ah[mt][3]);
                ldsm4(smb + OXLO + aoff2 + mt * 16 * (SX * 2) + kb, al[mt][0], al[mt][1], al[mt][2], al[mt][3]);
            }
            #pragma unroll
            for (int np = 0; np < 4; np++) {
                u32 bh[4], bl[4];
                ldsm4(w2hiB + boff2 + np * 16 * (SW * 2) + kb, bh[0], bh[1], bh[2], bh[3]);
                ldsm4(w2hiB + 9216 + boff2 + np * 16 * (SW * 2) + kb, bl[0], bl[1], bl[2], bl[3]);
                #pragma unroll
                for (int mt = 0; mt < 2; mt++) {
                    #pragma unroll
                    for (int hh = 0; hh < 2; hh++) {
                        float* c = acc2[mt][np * 2 + hh];
                        mma16816(c, ah[mt], bh[2 * hh], bh[2 * hh + 1]);
                        mma16816(c, ah[mt], bl[2 * hh], bl[2 * hh + 1]);
                        mma16816(c, al[mt], bh[2 * hh], bh[2 * hh + 1]);
                    }
                }
            }
        }

        // ---- epilogue2: bias + e' store + fused head ----
        {
            float L0[2][2], L1[2][2], NR[2][2];
            #pragma unroll
            for (int mt = 0; mt < 2; mt++)
                #pragma unroll
                for (int hh = 0; hh < 2; hh++) { L0[mt][hh] = 0.f; L1[mt][hh] = 0.f; NR[mt][hh] = 0.f; }

            #pragma unroll
            for (int mt = 0; mt < 2; mt++) {
                int rowa = m0 + mt * 16 + (l >> 2);
                int pa = ((j0 + rowa) << 1) | side;
                int pb = ((j0 + rowa + 8) << 1) | side;
                float* ea = g_e[dst] + ((size_t)b * N_ + pa) * 64;
                float* ebp = g_e[dst] + ((size_t)b * N_ + pb) * 64;
                #pragma unroll
                for (int nt = 0; nt < 8; nt++) {
                    float* c = acc2[mt][nt];
                    int col = nt * 8 + (l & 3) * 2;          // 0..63 output dim
                    float b0 = sB2[side * 64 + col], b1v = sB2[side * 64 + col + 1];
                    float o00 = c[0] + b0, o01 = c[1] + b1v;
                    float o10 = c[2] + b0, o11 = c[3] + b1v;
                    *(float2*)(ea + col)  = make_float2(o00, o01);
                    *(float2*)(ebp + col) = make_float2(o10, o11);
                    float w0 = sLW[col * 2], w1 = sLW[col * 2 + 1];
                    float w2 = sLW[col * 2 + 2], w3 = sLW[col * 2 + 3];
                    L0[mt][0] += o00 * w0 + o01 * w2;
                    L1[mt][0] += o00 * w1 + o01 * w3;
                    NR[mt][0] += o00 * o00 + o01 * o01;
                    L0[mt][1] += o10 * w0 + o11 * w2;
                    L1[mt][1] += o10 * w1 + o11 * w3;
                    NR[mt][1] += o10 * o10 + o11 * o11;
                }
            }
            // reduce across the 4 lanes sharing each row
            #pragma unroll
            for (int off = 2; off >= 1; off >>= 1) {
                #pragma unroll
                for (int mt = 0; mt < 2; mt++)
                    #pragma unroll
                    for (int hh = 0; hh < 2; hh++) {
                        L0[mt][hh] += __shfl_xor_sync(0xffffffffu, L0[mt][hh], off);
                        L1[mt][hh] += __shfl_xor_sync(0xffffffffu, L1[mt][hh], off);
                        NR[mt][hh] += __shfl_xor_sync(0xffffffffu, NR[mt][hh], off);
                    }
            }
            if ((l & 3) == 0) {
                #pragma unroll
                for (int mt = 0; mt < 2; mt++) {
                    #pragma unroll
                    for (int hh = 0; hh < 2; hh++) {
                        int r = m0 + mt * 16 + (l >> 2) + hh * 8;
                        int p = ((j0 + r) << 1) | side;
                        unsigned char vp = side ? sVe[r] : sVx[r];
                        g_v[dst][b * N_ + p] = vp;
                        float l0 = L0[mt][hh] + lb0, l1 = L1[mt][hh] + lb1;
                        float mm = fmaxf(l0, l1);
                        float x0 = expf(l0 - mm), x1 = expf(l1 - mm);
                        float inv = 1.f / (x0 + x1);
                        float p0 = x0 * inv, p1 = x1 * inv;
                        float pt = vp ? p1 : p0;
                        float loss = -logf(fminf(fmaxf(pt, 1e-7f), 1.f));
                        out[(size_t)b * (11 * N_) + (size_t)s * N_ + p] = loss;
                        float2* pr = (float2*)(out + PRED_OFF + (((size_t)(b * N_ + p)) * 11 + s) * 2);
                        *pr = make_float2(p0, p1);
                        out[NORM_OFF + (size_t)b * (11 * N_) + (size_t)s * N_ + p] = sqrtf(NR[mt][hh]);
                    }
                }
            }
        }
        __syncthreads();   // protect H buffer + bits before next tile
    }
}

// ---------------- launch ----------------
extern "C" void kernel_launch(void* const* d_in, const int* in_sizes, int n_in,
                              void* d_out, int out_size) {
    const int*   x    = (const int*)d_in[0];
    const float* y    = (const float*)d_in[1];
    const float* embW = (const float*)d_in[2];
    const float* embb = (const float*)d_in[3];
    const float* lab  = (const float*)d_in[4];
    const float* cnW1 = (const float*)d_in[5];
    const float* cnb1 = (const float*)d_in[6];
    const float* cnW2 = (const float*)d_in[7];
    const float* cnb2 = (const float*)d_in[8];
    const float* bnW1 = (const float*)d_in[9];
    const float* bnb1 = (const float*)d_in[10];
    const float* bnW2 = (const float*)d_in[11];
    const float* bnb2 = (const float*)d_in[12];
    const float* llrW = (const float*)d_in[13];
    const float* llrb = (const float*)d_in[14];
    float* out = (float*)d_out;

    cudaFuncSetAttribute(stage_kernel, cudaFuncAttributeMaxDynamicSharedMemorySize, DSMEM_BYTES);

    prep_kernel<<<1, 256>>>(cnW1, bnW1, cnW2, bnW2, cnb1, bnb1, cnb2, bnb2, lab);
    stage0_kernel<<<(B_ * N_ * 16) / 256, 256>>>(x, y, embW, embb, llrW, llrb, out);
    for (int s = 1; s <= 10; s++) {
        stage_kernel<<<152, 256, DSMEM_BYTES>>>(1 << s, (s - 1) & 1, s, llrW, llrb, out);
    }
}